// round 14
// baseline (speedup 1.0000x reference)
#include <cuda_runtime.h>
#include <cuda_fp16.h>
#include <cstdint>

// Problem constants (fixed shapes)
#define NNODES 10000
#define NEDGES 640000
#define CIN    128
#define COUT   128
#define HDIM   256
#define BN_EPS 1e-5f

// ---------------------------------------------------------------------------
// Scratch (__device__ globals; no allocation allowed)
// ---------------------------------------------------------------------------
__device__ __align__(16) __half g_ABh[NNODES * 512];  // [n][0:256]=A' (dst), [n][256:512]=B (src)
__device__ __align__(16) __half g_W2h[COUT * HDIM];   // W2^T [n][k], fp16
__device__ int    g_src[NEDGES];
__device__ int    g_dst[NEDGES];
__device__ int    g_ssrc[NEDGES];   // dst-sorted
__device__ int    g_sdst[NEDGES];
__device__ int    g_cnt[NNODES];
__device__ int    g_cur[NNODES];

// ---------------------------------------------------------------------------
// fp16 mma m16n8k16 (fp32 accumulate) + ldmatrix helpers
// ---------------------------------------------------------------------------
__device__ __forceinline__ void mma_f16(float& c0, float& c1, float& c2, float& c3,
                                        uint32_t a0, uint32_t a1, uint32_t a2, uint32_t a3,
                                        uint32_t b0, uint32_t b1) {
    asm volatile(
        "mma.sync.aligned.m16n8k16.row.col.f32.f16.f16.f32 "
        "{%0,%1,%2,%3}, {%4,%5,%6,%7}, {%8,%9}, {%0,%1,%2,%3};\n"
        : "+f"(c0), "+f"(c1), "+f"(c2), "+f"(c3)
        : "r"(a0), "r"(a1), "r"(a2), "r"(a3), "r"(b0), "r"(b1));
}

__device__ __forceinline__ void ldsm_x4(uint32_t& r0, uint32_t& r1, uint32_t& r2, uint32_t& r3,
                                        uint32_t addr) {
    asm volatile("ldmatrix.sync.aligned.m8n8.x4.shared.b16 {%0,%1,%2,%3}, [%4];"
                 : "=r"(r0), "=r"(r1), "=r"(r2), "=r"(r3) : "r"(addr));
}

// ---------------------------------------------------------------------------
// Launch #1: fused detect + extract + zero-output + zero-histogram
// ---------------------------------------------------------------------------
__global__ void extract_fused_kernel(const int* __restrict__ w, float4* __restrict__ out4) {
    const int tid = threadIdx.x;
    const int i = blockIdx.x * 256 + tid;
    int v = (i < NEDGES) ? w[2 * i + 1] : 0;
    const int is64 = !__syncthreads_or(v != 0);   // block-wide verdict, globally consistent

    if (i < NNODES * COUT / 4) out4[i] = make_float4(0.f, 0.f, 0.f, 0.f);
    if (i < NNODES) g_cnt[i] = 0;

    if (i >= NEDGES) return;
    int s, d;
    if (is64) {
        s = w[2 * i];
        d = w[2 * (NEDGES + i)];
    } else {
        s = w[i];
        d = w[NEDGES + i];
    }
    g_src[i] = min(max(s, 0), NNODES - 1);
    g_dst[i] = min(max(d, 0), NNODES - 1);
}

// ---------------------------------------------------------------------------
// Launches #2-4: counting sort by dst (hist -> scan -> scatter)
// ---------------------------------------------------------------------------
__global__ void hist_kernel() {
    int i = blockIdx.x * blockDim.x + threadIdx.x;
    if (i < NEDGES) atomicAdd(&g_cnt[g_dst[i]], 1);
}

__global__ __launch_bounds__(1024) void scan_kernel() {
    __shared__ int wsum[32];
    int t = threadIdx.x;
    const int PER = 10;
    int base = t * PER;
    int loc[PER];
    int s = 0;
    #pragma unroll
    for (int i = 0; i < PER; ++i) {
        int b = base + i;
        loc[i] = s;
        if (b < NNODES) s += g_cnt[b];
    }
    int lane = t & 31, wid = t >> 5;
    int incl = s;
    #pragma unroll
    for (int o = 1; o < 32; o <<= 1) {
        int v = __shfl_up_sync(~0u, incl, o);
        if (lane >= o) incl += v;
    }
    if (lane == 31) wsum[wid] = incl;
    __syncthreads();
    if (wid == 0) {
        int v = wsum[lane];
        #pragma unroll
        for (int o = 1; o < 32; o <<= 1) {
            int u = __shfl_up_sync(~0u, v, o);
            if (lane >= o) v += u;
        }
        wsum[lane] = v;
    }
    __syncthreads();
    int pre = incl - s + (wid ? wsum[wid - 1] : 0);
    #pragma unroll
    for (int i = 0; i < PER; ++i) {
        int b = base + i;
        if (b < NNODES) g_cur[b] = pre + loc[i];
    }
}

__global__ void scatter_kernel() {
    int i = blockIdx.x * blockDim.x + threadIdx.x;
    if (i >= NEDGES) return;
    int d = g_dst[i];
    int pos = atomicAdd(&g_cur[d], 1);
    g_sdst[pos] = d;
    g_ssrc[pos] = g_src[i];
}

// ---------------------------------------------------------------------------
// Launch #5: fused prep + node GEMM on fp16 tensor cores (unchanged)
// ---------------------------------------------------------------------------
#define XS 136

__global__ __launch_bounds__(256) void gemm_fused_kernel(
    const float* __restrict__ x,
    const float* __restrict__ gamma, const float* __restrict__ beta,
    const float* __restrict__ mean, const float* __restrict__ var,
    const float* __restrict__ W1, const float* __restrict__ b1) {
    __shared__ float s_sh[CIN], t_sh[CIN];
    __shared__ float dvp[4 * 64];
    __shared__ float dv_s[64];
    __shared__ __half xs[64 * XS];
    __shared__ __half wt[64 * XS];

    const int tid = threadIdx.x;
    const int m0 = blockIdx.x * 64, n0 = blockIdx.y * 64;

    if (tid < CIN) {
        float s = gamma[tid] * rsqrtf(var[tid] + BN_EPS);
        s_sh[tid] = s;
        t_sh[tid] = beta[tid] - mean[tid] * s;
    }
    __syncthreads();

    {
        int jj = tid & 63;
        int kg = tid >> 6;
        int j = n0 + jj;
        float dacc = 0.f;
        #pragma unroll 4
        for (int k = kg * 32; k < kg * 32 + 32; ++k) {
            float wc;
            if (j < HDIM) wc = W1[k * HDIM + j] - W1[(k + CIN) * HDIM + j];
            else          wc = W1[(k + CIN) * HDIM + (j - HDIM)];
            wt[jj * XS + k] = __float2half_rn(s_sh[k] * wc);
            dacc += t_sh[k] * wc;
        }
        dvp[kg * 64 + jj] = dacc;
    }

    {
        int row = tid >> 2, q = tid & 3;
        bool ok = (m0 + row) < NNODES;
        const float* xr = x + (m0 + row) * CIN + q * 32;
        #pragma unroll
        for (int i = 0; i < 8; ++i) {
            float4 v = ok ? *(const float4*)(xr + i * 4) : make_float4(0.f, 0.f, 0.f, 0.f);
            __half2 h0 = __floats2half2_rn(v.x, v.y);
            __half2 h1 = __floats2half2_rn(v.z, v.w);
            uint2 o;
            o.x = *(uint32_t*)&h0;
            o.y = *(uint32_t*)&h1;
            *(uint2*)&xs[row * XS + q * 32 + i * 4] = o;
        }
    }
    __syncthreads();

    if (tid < 64) {
        int j = n0 + tid;
        dv_s[tid] = dvp[tid] + dvp[64 + tid] + dvp[128 + tid] + dvp[192 + tid]
                  + ((j < HDIM) ? b1[j] : 0.f);
    }

    const int lane = tid & 31;
    const int w    = tid >> 5;
    const int wm   = w & 1;
    const int wn   = w >> 1;
    const int g    = lane >> 2;
    const int tg   = lane & 3;
    const int mat  = lane >> 3, r8 = lane & 7;

    const uint32_t xs_addr = (uint32_t)__cvta_generic_to_shared(xs);
    const uint32_t wt_addr = (uint32_t)__cvta_generic_to_shared(wt);
    uint32_t aBase[2];
    #pragma unroll
    for (int mt = 0; mt < 2; ++mt) {
        int row = wm * 32 + mt * 16 + (mat & 1) * 8 + r8;
        aBase[mt] = xs_addr + (row * XS + (mat >> 1) * 8) * 2;
    }
    const uint32_t bBase = wt_addr + ((wn * 16 + (mat >> 1) * 8 + r8) * XS + (mat & 1) * 8) * 2;

    float acc[2][2][4];
    #pragma unroll
    for (int mt = 0; mt < 2; ++mt)
        #pragma unroll
        for (int nt = 0; nt < 2; ++nt)
            #pragma unroll
            for (int i = 0; i < 4; ++i) acc[mt][nt][i] = 0.f;

    #pragma unroll
    for (int ks = 0; ks < CIN / 16; ++ks) {
        uint32_t kb = ks * 32;
        uint32_t a[2][4];
        #pragma unroll
        for (int mt = 0; mt < 2; ++mt)
            ldsm_x4(a[mt][0], a[mt][1], a[mt][2], a[mt][3], aBase[mt] + kb);
        uint32_t b[2][2];
        ldsm_x4(b[0][0], b[0][1], b[1][0], b[1][1], bBase + kb);
        #pragma unroll
        for (int mt = 0; mt < 2; ++mt)
            #pragma unroll
            for (int nt = 0; nt < 2; ++nt)
                mma_f16(acc[mt][nt][0], acc[mt][nt][1], acc[mt][nt][2], acc[mt][nt][3],
                        a[mt][0], a[mt][1], a[mt][2], a[mt][3],
                        b[nt][0], b[nt][1]);
    }
    __syncthreads();

    #pragma unroll
    for (int mt = 0; mt < 2; ++mt) {
        #pragma unroll
        for (int nt = 0; nt < 2; ++nt) {
            int lc = wn * 16 + nt * 8 + tg * 2;
            float d0 = dv_s[lc], d1 = dv_s[lc + 1];
            #pragma unroll
            for (int r = 0; r < 2; ++r) {
                int row = m0 + wm * 32 + mt * 16 + g + r * 8;
                if (row < NNODES) {
                    __half2 h = __floats2half2_rn(acc[mt][nt][2 * r] + d0,
                                                  acc[mt][nt][2 * r + 1] + d1);
                    *(uint32_t*)&g_ABh[row * 512 + n0 + lc] = *(uint32_t*)&h;
                }
            }
        }
    }
}

// ---------------------------------------------------------------------------
// Launch #6: W2 transpose to [n][k] fp16
// ---------------------------------------------------------------------------
__global__ void prep_w2t(const float* __restrict__ W2) {
    int idx = blockIdx.x * 256 + threadIdx.x;
    if (idx < COUT * HDIM) {
        int n = idx >> 8, k = idx & 255;
        g_W2h[idx] = __float2half_rn(W2[k * COUT + n]);
    }
}

// ---------------------------------------------------------------------------
// Launch #7: persistent edge kernel on dst-SORTED edges.
// R13 structure (4 x 4-warp groups, 32x64 warp tiles) plus:
//  - gather A-row register cache (reload only on dst change; warp-uniform)
//  - epilogue atomics collapsed 4->1 when the thread's 4 rows share a dst
// ---------------------------------------------------------------------------
#define TILE_E 64
#define KS 264                        // half stride per row; conflict-free ldsm
#define NT64 (NEDGES / TILE_E)        // 10000

#define W2_HALVES (COUT * KS)         // 33792
#define H_HALVES  (TILE_E * KS)       // 16896
#define SMEM_BYTES ((W2_HALVES + 4 * H_HALVES) * 2 + COUT * 4)   // 203264 B

__global__ __launch_bounds__(512, 1) void edge_kernel(const float* __restrict__ b2,
                                                      int* __restrict__ outI) {
    extern __shared__ __half smem[];
    __half* W2_s = smem;                          // [128][KS]
    __half* hbase = smem + W2_HALVES;             // 4 x [64][KS]
    float*  b2_s = (float*)(hbase + 4 * H_HALVES);// [128]

    const int tid  = threadIdx.x;
    const int lane = tid & 31;
    const int w    = tid >> 5;        // 0..15
    const int grp  = w >> 2;          // group 0..3
    const int ww   = w & 3;           // warp within group
    const int wm   = ww & 1;          // row band (32 rows)
    const int wn   = ww >> 1;         // col band (64 cols)
    const int gg   = lane >> 2;
    const int tg   = lane & 3;

    // W2^T into smem once (512 threads)
    for (int idx = tid; idx < COUT * HDIM / 8; idx += 512) {
        int n = idx >> 5, kc = (idx & 31) * 8;
        *(uint4*)&W2_s[n * KS + kc] = *(const uint4*)&g_W2h[n * HDIM + kc];
    }
    if (tid < COUT) b2_s[tid] = b2[tid];
    __syncthreads();

    __half* hb = hbase + grp * H_HALVES;
    const uint32_t h_addr  = (uint32_t)__cvta_generic_to_shared(hb);
    const uint32_t w2_addr = (uint32_t)__cvta_generic_to_shared(W2_s);
    const int mat = lane >> 3, r8 = lane & 7;
    uint32_t aBase[2];
    #pragma unroll
    for (int mt = 0; mt < 2; ++mt) {
        int row = wm * 32 + mt * 16 + (mat & 1) * 8 + r8;
        aBase[mt] = h_addr + (row * KS + (mat >> 1) * 8) * 2;
    }
    uint32_t bBase[4];
    #pragma unroll
    for (int p = 0; p < 4; ++p) {
        int n = wn * 64 + p * 16 + (mat >> 1) * 8 + r8;
        bBase[p] = w2_addr + (n * KS + (mat & 1) * 8) * 2;
    }

    // b2 pairs cached in registers
    float2 b2p[8];
    #pragma unroll
    for (int nt = 0; nt < 8; ++nt)
        b2p[nt] = *(float2*)&b2_s[wn * 64 + nt * 8 + tg * 2];

    const int kc8 = lane * 8;
    const int barid = grp + 1;

    for (int tile = blockIdx.x * 4 + grp; tile < NT64; tile += gridDim.x * 4) {
        const int ebase = tile * TILE_E;

        // Stage 1: gather + relu -> hb; A-row cached in regs (dst-sorted)
        const __half2 z2 = __float2half2_rn(0.f);
        {
            int dprev = -1;
            uint4 ua = make_uint4(0u, 0u, 0u, 0u);
            #pragma unroll 4
            for (int pass = 0; pass < 16; ++pass) {
                int row = pass * 4 + ww;
                int d = __ldg(&g_sdst[ebase + row]);
                int s = __ldg(&g_ssrc[ebase + row]);
                if (d != dprev) {               // warp-uniform (d is per-row)
                    ua = *(const uint4*)&g_ABh[d * 512 + kc8];
                    dprev = d;
                }
                uint4 ub = *(const uint4*)&g_ABh[s * 512 + 256 + kc8];
                uint4 o;
                __half2 h;
                h = __hmax2(__hadd2(*(__half2*)&ua.x, *(__half2*)&ub.x), z2); o.x = *(uint32_t*)&h;
                h = __hmax2(__hadd2(*(__half2*)&ua.y, *(__half2*)&ub.y), z2); o.y = *(uint32_t*)&h;
                h = __hmax2(__hadd2(*(__half2*)&ua.z, *(__half2*)&ub.z), z2); o.z = *(uint32_t*)&h;
                h = __hmax2(__hadd2(*(__half2*)&ua.w, *(__half2*)&ub.w), z2); o.w = *(uint32_t*)&h;
                *(uint4*)&hb[row * KS + kc8] = o;
            }
        }
        asm volatile("bar.sync %0, 128;" :: "r"(barid) : "memory");

        // Stage 2: fp16 mma, warp tile 32x64, group tile [64x256] @ [256x128]
        float acc[2][8][4];
        #pragma unroll
        for (int mt = 0; mt < 2; ++mt)
            #pragma unroll
            for (int nt = 0; nt < 8; ++nt)
                #pragma unroll
                for (int i = 0; i < 4; ++i) acc[mt][nt][i] = 0.f;

        #pragma unroll 4
        for (int ks = 0; ks < HDIM / 16; ++ks) {
            uint32_t kb = ks * 32;
            uint32_t a[2][4];
            #pragma unroll
            for (int mt = 0; mt < 2; ++mt)
                ldsm_x4(a[mt][0], a[mt][1], a[mt][2], a[mt][3], aBase[mt] + kb);
            uint32_t b[8][2];
            #pragma unroll
            for (int p = 0; p < 4; ++p)
                ldsm_x4(b[2 * p][0], b[2 * p][1], b[2 * p + 1][0], b[2 * p + 1][1],
                        bBase[p] + kb);
            #pragma unroll
            for (int mt = 0; mt < 2; ++mt)
                #pragma unroll
                for (int nt = 0; nt < 8; ++nt)
                    mma_f16(acc[mt][nt][0], acc[mt][nt][1], acc[mt][nt][2], acc[mt][nt][3],
                            a[mt][0], a[mt][1], a[mt][2], a[mt][3],
                            b[nt][0], b[nt][1]);
        }

        // Epilogue (registers + atomics; before barrier, overlaps peers' mma).
        // Sorted dst: the thread's 4 rows usually share one dst -> collapse
        // 4 atomics into 1 via register max (max is exact; output identical).
        int drow[2][2];
        #pragma unroll
        for (int mt = 0; mt < 2; ++mt)
            #pragma unroll
            for (int r = 0; r < 2; ++r)
                drow[mt][r] = __ldg(&g_sdst[ebase + wm * 32 + mt * 16 + gg + r * 8]);

        bool same = (drow[0][0] == drow[0][1]) & (drow[0][0] == drow[1][0]) &
                    (drow[0][0] == drow[1][1]);

        #pragma unroll
        for (int nt = 0; nt < 8; ++nt) {
            int col = wn * 64 + nt * 8 + tg * 2;
            #pragma unroll
            for (int par = 0; par < 2; ++par) {
                float b2v = par ? b2p[nt].y : b2p[nt].x;
                if (same) {
                    float v = fmaxf(fmaxf(acc[0][nt][par], acc[0][nt][2 + par]),
                                    fmaxf(acc[1][nt][par], acc[1][nt][2 + par])) + b2v;
                    if (v > 0.f)
                        atomicMax(outI + drow[0][0] * COUT + col + par, __float_as_int(v));
                } else {
                    #pragma unroll
                    for (int mt = 0; mt < 2; ++mt)
                        #pragma unroll
                        for (int r = 0; r < 2; ++r) {
                            float v = acc[mt][nt][2 * r + par] + b2v;
                            if (v > 0.f)
                                atomicMax(outI + drow[mt][r] * COUT + col + par,
                                          __float_as_int(v));
                        }
                }
            }
        }

        // Protect hb (mma reads) from next iteration's gather writes
        asm volatile("bar.sync %0, 128;" :: "r"(barid) : "memory");
    }
}

// ---------------------------------------------------------------------------
// Launch — 7 kernels (sort added); edge_kernel last
// ---------------------------------------------------------------------------
extern "C" void kernel_launch(void* const* d_in, const int* in_sizes, int n_in,
                              void* d_out, int out_size) {
    const float* x        = (const float*)d_in[0];
    const int*   eiw      = (const int*)d_in[1];
    const float* bn_gamma = (const float*)d_in[2];
    const float* bn_beta  = (const float*)d_in[3];
    const float* bn_mean  = (const float*)d_in[4];
    const float* bn_var   = (const float*)d_in[5];
    const float* W1       = (const float*)d_in[6];
    const float* b1       = (const float*)d_in[7];
    const float* W2       = (const float*)d_in[8];
    const float* b2       = (const float*)d_in[9];

    cudaFuncSetAttribute(edge_kernel, cudaFuncAttributeMaxDynamicSharedMemorySize, SMEM_BYTES);

    extract_fused_kernel<<<(NEDGES + 255) / 256, 256>>>(eiw, (float4*)d_out);      // 1
    hist_kernel<<<(NEDGES + 255) / 256, 256>>>();                                  // 2
    scan_kernel<<<1, 1024>>>();                                                    // 3
    scatter_kernel<<<(NEDGES + 255) / 256, 256>>>();                               // 4
    dim3 g1((NNODES + 63) / 64, 512 / 64);
    gemm_fused_kernel<<<g1, 256>>>(x, bn_gamma, bn_beta, bn_mean, bn_var, W1, b1); // 5
    prep_w2t<<<128, 256>>>(W2);                                                    // 6
    edge_kernel<<<152, 512, SMEM_BYTES>>>(b2, (int*)d_out);                        // 7
}

// round 15
// speedup vs baseline: 1.1346x; 1.1346x over previous
#include <cuda_runtime.h>
#include <cuda_fp16.h>
#include <cstdint>

// Problem constants (fixed shapes)
#define NNODES 10000
#define NEDGES 640000
#define CIN    128
#define COUT   128
#define HDIM   256
#define BN_EPS 1e-5f

// ---------------------------------------------------------------------------
// Scratch (__device__ globals; no allocation allowed)
// ---------------------------------------------------------------------------
__device__ __align__(16) __half g_ABh[NNODES * 512];  // [n][0:256]=A' (dst), [n][256:512]=B (src)
__device__ __align__(16) __half g_W2h[COUT * HDIM];   // W2^T [n][k], fp16
__device__ int    g_src[NEDGES];
__device__ int    g_dst[NEDGES];
__device__ int    g_tilectr;                          // dynamic tile ticket

// ---------------------------------------------------------------------------
// fp16 mma m16n8k16 (fp32 accumulate) + ldmatrix helpers
// ---------------------------------------------------------------------------
__device__ __forceinline__ void mma_f16(float& c0, float& c1, float& c2, float& c3,
                                        uint32_t a0, uint32_t a1, uint32_t a2, uint32_t a3,
                                        uint32_t b0, uint32_t b1) {
    asm volatile(
        "mma.sync.aligned.m16n8k16.row.col.f32.f16.f16.f32 "
        "{%0,%1,%2,%3}, {%4,%5,%6,%7}, {%8,%9}, {%0,%1,%2,%3};\n"
        : "+f"(c0), "+f"(c1), "+f"(c2), "+f"(c3)
        : "r"(a0), "r"(a1), "r"(a2), "r"(a3), "r"(b0), "r"(b1));
}

__device__ __forceinline__ void ldsm_x4(uint32_t& r0, uint32_t& r1, uint32_t& r2, uint32_t& r3,
                                        uint32_t addr) {
    asm volatile("ldmatrix.sync.aligned.m8n8.x4.shared.b16 {%0,%1,%2,%3}, [%4];"
                 : "=r"(r0), "=r"(r1), "=r"(r2), "=r"(r3) : "r"(addr));
}

// ---------------------------------------------------------------------------
// Launch #1: fused detect + extract + zero-output + ticket reset
// ---------------------------------------------------------------------------
__global__ void extract_fused_kernel(const int* __restrict__ w, float4* __restrict__ out4) {
    const int tid = threadIdx.x;
    const int i = blockIdx.x * 256 + tid;
    int v = (i < NEDGES) ? w[2 * i + 1] : 0;
    const int is64 = !__syncthreads_or(v != 0);   // block-wide verdict, globally consistent

    if (i == 0) g_tilectr = 152 * 4;              // first 608 tiles statically assigned
    if (i < NNODES * COUT / 4) out4[i] = make_float4(0.f, 0.f, 0.f, 0.f);

    if (i >= NEDGES) return;
    int s, d;
    if (is64) {
        s = w[2 * i];
        d = w[2 * (NEDGES + i)];
    } else {
        s = w[i];
        d = w[NEDGES + i];
    }
    g_src[i] = min(max(s, 0), NNODES - 1);
    g_dst[i] = min(max(d, 0), NNODES - 1);
}

// ---------------------------------------------------------------------------
// Launch #2: fused prep + node GEMM on fp16 tensor cores
// ---------------------------------------------------------------------------
#define XS 136

__global__ __launch_bounds__(256) void gemm_fused_kernel(
    const float* __restrict__ x,
    const float* __restrict__ gamma, const float* __restrict__ beta,
    const float* __restrict__ mean, const float* __restrict__ var,
    const float* __restrict__ W1, const float* __restrict__ b1) {
    __shared__ float s_sh[CIN], t_sh[CIN];
    __shared__ float dvp[4 * 64];
    __shared__ float dv_s[64];
    __shared__ __half xs[64 * XS];
    __shared__ __half wt[64 * XS];

    const int tid = threadIdx.x;
    const int m0 = blockIdx.x * 64, n0 = blockIdx.y * 64;

    if (tid < CIN) {
        float s = gamma[tid] * rsqrtf(var[tid] + BN_EPS);
        s_sh[tid] = s;
        t_sh[tid] = beta[tid] - mean[tid] * s;
    }
    __syncthreads();

    {
        int jj = tid & 63;
        int kg = tid >> 6;
        int j = n0 + jj;
        float dacc = 0.f;
        #pragma unroll 4
        for (int k = kg * 32; k < kg * 32 + 32; ++k) {
            float wc;
            if (j < HDIM) wc = W1[k * HDIM + j] - W1[(k + CIN) * HDIM + j];
            else          wc = W1[(k + CIN) * HDIM + (j - HDIM)];
            wt[jj * XS + k] = __float2half_rn(s_sh[k] * wc);
            dacc += t_sh[k] * wc;
        }
        dvp[kg * 64 + jj] = dacc;
    }

    {
        int row = tid >> 2, q = tid & 3;
        bool ok = (m0 + row) < NNODES;
        const float* xr = x + (m0 + row) * CIN + q * 32;
        #pragma unroll
        for (int i = 0; i < 8; ++i) {
            float4 v = ok ? *(const float4*)(xr + i * 4) : make_float4(0.f, 0.f, 0.f, 0.f);
            __half2 h0 = __floats2half2_rn(v.x, v.y);
            __half2 h1 = __floats2half2_rn(v.z, v.w);
            uint2 o;
            o.x = *(uint32_t*)&h0;
            o.y = *(uint32_t*)&h1;
            *(uint2*)&xs[row * XS + q * 32 + i * 4] = o;
        }
    }
    __syncthreads();

    if (tid < 64) {
        int j = n0 + tid;
        dv_s[tid] = dvp[tid] + dvp[64 + tid] + dvp[128 + tid] + dvp[192 + tid]
                  + ((j < HDIM) ? b1[j] : 0.f);
    }

    const int lane = tid & 31;
    const int w    = tid >> 5;
    const int wm   = w & 1;
    const int wn   = w >> 1;
    const int g    = lane >> 2;
    const int tg   = lane & 3;
    const int mat  = lane >> 3, r8 = lane & 7;

    const uint32_t xs_addr = (uint32_t)__cvta_generic_to_shared(xs);
    const uint32_t wt_addr = (uint32_t)__cvta_generic_to_shared(wt);
    uint32_t aBase[2];
    #pragma unroll
    for (int mt = 0; mt < 2; ++mt) {
        int row = wm * 32 + mt * 16 + (mat & 1) * 8 + r8;
        aBase[mt] = xs_addr + (row * XS + (mat >> 1) * 8) * 2;
    }
    const uint32_t bBase = wt_addr + ((wn * 16 + (mat >> 1) * 8 + r8) * XS + (mat & 1) * 8) * 2;

    float acc[2][2][4];
    #pragma unroll
    for (int mt = 0; mt < 2; ++mt)
        #pragma unroll
        for (int nt = 0; nt < 2; ++nt)
            #pragma unroll
            for (int i = 0; i < 4; ++i) acc[mt][nt][i] = 0.f;

    #pragma unroll
    for (int ks = 0; ks < CIN / 16; ++ks) {
        uint32_t kb = ks * 32;
        uint32_t a[2][4];
        #pragma unroll
        for (int mt = 0; mt < 2; ++mt)
            ldsm_x4(a[mt][0], a[mt][1], a[mt][2], a[mt][3], aBase[mt] + kb);
        uint32_t b[2][2];
        ldsm_x4(b[0][0], b[0][1], b[1][0], b[1][1], bBase + kb);
        #pragma unroll
        for (int mt = 0; mt < 2; ++mt)
            #pragma unroll
            for (int nt = 0; nt < 2; ++nt)
                mma_f16(acc[mt][nt][0], acc[mt][nt][1], acc[mt][nt][2], acc[mt][nt][3],
                        a[mt][0], a[mt][1], a[mt][2], a[mt][3],
                        b[nt][0], b[nt][1]);
    }
    __syncthreads();

    #pragma unroll
    for (int mt = 0; mt < 2; ++mt) {
        #pragma unroll
        for (int nt = 0; nt < 2; ++nt) {
            int lc = wn * 16 + nt * 8 + tg * 2;
            float d0 = dv_s[lc], d1 = dv_s[lc + 1];
            #pragma unroll
            for (int r = 0; r < 2; ++r) {
                int row = m0 + wm * 32 + mt * 16 + g + r * 8;
                if (row < NNODES) {
                    __half2 h = __floats2half2_rn(acc[mt][nt][2 * r] + d0,
                                                  acc[mt][nt][2 * r + 1] + d1);
                    *(uint32_t*)&g_ABh[row * 512 + n0 + lc] = *(uint32_t*)&h;
                }
            }
        }
    }
}

// ---------------------------------------------------------------------------
// Launch #3: W2 transpose to [n][k] fp16
// ---------------------------------------------------------------------------
__global__ void prep_w2t(const float* __restrict__ W2) {
    int idx = blockIdx.x * 256 + threadIdx.x;
    if (idx < COUT * HDIM) {
        int n = idx >> 8, k = idx & 255;
        g_W2h[idx] = __float2half_rn(W2[k * COUT + n]);
    }
}

// ---------------------------------------------------------------------------
// Launch #4: persistent edge kernel — R13 champion shape (4 x 4-warp groups,
// 32x64 warp tiles, register b2, epilogue-before-barrier) + dynamic tile
// scheduling via global ticket counter (fetch overlaps the existing barrier).
// ---------------------------------------------------------------------------
#define TILE_E 64
#define KS 264                        // half stride per row; conflict-free ldsm
#define NT64 (NEDGES / TILE_E)        // 10000

#define W2_HALVES (COUT * KS)         // 33792
#define H_HALVES  (TILE_E * KS)       // 16896
#define SMEM_BYTES ((W2_HALVES + 4 * H_HALVES) * 2 + COUT * 4 + 16)

__global__ __launch_bounds__(512, 1) void edge_kernel(const float* __restrict__ b2,
                                                      int* __restrict__ outI) {
    extern __shared__ __half smem[];
    __half* W2_s = smem;                          // [128][KS]
    __half* hbase = smem + W2_HALVES;             // 4 x [64][KS]
    float*  b2_s = (float*)(hbase + 4 * H_HALVES);// [128]
    int*    tile_s = (int*)(b2_s + COUT);         // [4] next-tile slots

    const int tid  = threadIdx.x;
    const int lane = tid & 31;
    const int w    = tid >> 5;        // 0..15
    const int grp  = w >> 2;          // group 0..3
    const int ww   = w & 3;           // warp within group
    const int wm   = ww & 1;          // row band (32 rows)
    const int wn   = ww >> 1;         // col band (64 cols)
    const int gg   = lane >> 2;
    const int tg   = lane & 3;

    // W2^T into smem once (512 threads)
    for (int idx = tid; idx < COUT * HDIM / 8; idx += 512) {
        int n = idx >> 5, kc = (idx & 31) * 8;
        *(uint4*)&W2_s[n * KS + kc] = *(const uint4*)&g_W2h[n * HDIM + kc];
    }
    if (tid < COUT) b2_s[tid] = b2[tid];
    __syncthreads();

    __half* hb = hbase + grp * H_HALVES;
    const uint32_t h_addr  = (uint32_t)__cvta_generic_to_shared(hb);
    const uint32_t w2_addr = (uint32_t)__cvta_generic_to_shared(W2_s);
    const int mat = lane >> 3, r8 = lane & 7;
    uint32_t aBase[2];
    #pragma unroll
    for (int mt = 0; mt < 2; ++mt) {
        int row = wm * 32 + mt * 16 + (mat & 1) * 8 + r8;
        aBase[mt] = h_addr + (row * KS + (mat >> 1) * 8) * 2;
    }
    uint32_t bBase[4];
    #pragma unroll
    for (int p = 0; p < 4; ++p) {
        int n = wn * 64 + p * 16 + (mat >> 1) * 8 + r8;
        bBase[p] = w2_addr + (n * KS + (mat & 1) * 8) * 2;
    }

    // b2 pairs cached in registers: cols wn*64 + nt*8 + tg*2 (+1)
    float2 b2p[8];
    #pragma unroll
    for (int nt = 0; nt < 8; ++nt)
        b2p[nt] = *(float2*)&b2_s[wn * 64 + nt * 8 + tg * 2];

    const int kc8 = lane * 8;
    const int barid = grp + 1;

    int tile = blockIdx.x * 4 + grp;   // static seed; then dynamic tickets
    while (tile < NT64) {
        const int ebase = tile * TILE_E;

        // Stage 1: gather + relu -> hb (4 warps, warp = one row per pass, 16 passes)
        const __half2 z2 = __float2half2_rn(0.f);
        #pragma unroll
        for (int pass = 0; pass < 16; ++pass) {
            int row = pass * 4 + ww;
            int d = __ldg(&g_dst[ebase + row]);
            int s = __ldg(&g_src[ebase + row]);
            uint4 ua = *(const uint4*)&g_ABh[d * 512 + kc8];
            uint4 ub = *(const uint4*)&g_ABh[s * 512 + 256 + kc8];
            uint4 o;
            __half2 h;
            h = __hmax2(__hadd2(*(__half2*)&ua.x, *(__half2*)&ub.x), z2); o.x = *(uint32_t*)&h;
            h = __hmax2(__hadd2(*(__half2*)&ua.y, *(__half2*)&ub.y), z2); o.y = *(uint32_t*)&h;
            h = __hmax2(__hadd2(*(__half2*)&ua.z, *(__half2*)&ub.z), z2); o.z = *(uint32_t*)&h;
            h = __hmax2(__hadd2(*(__half2*)&ua.w, *(__half2*)&ub.w), z2); o.w = *(uint32_t*)&h;
            *(uint4*)&hb[row * KS + kc8] = o;
        }
        asm volatile("bar.sync %0, 128;" :: "r"(barid) : "memory");

        // Stage 2: fp16 mma, warp tile 32x64, group tile [64x256] @ [256x128]
        float acc[2][8][4];
        #pragma unroll
        for (int mt = 0; mt < 2; ++mt)
            #pragma unroll
            for (int nt = 0; nt < 8; ++nt)
                #pragma unroll
                for (int i = 0; i < 4; ++i) acc[mt][nt][i] = 0.f;

        #pragma unroll 4
        for (int ks = 0; ks < HDIM / 16; ++ks) {
            uint32_t kb = ks * 32;
            uint32_t a[2][4];
            #pragma unroll
            for (int mt = 0; mt < 2; ++mt)
                ldsm_x4(a[mt][0], a[mt][1], a[mt][2], a[mt][3], aBase[mt] + kb);
            uint32_t b[8][2];
            #pragma unroll
            for (int p = 0; p < 4; ++p)
                ldsm_x4(b[2 * p][0], b[2 * p][1], b[2 * p + 1][0], b[2 * p + 1][1],
                        bBase[p] + kb);
            #pragma unroll
            for (int mt = 0; mt < 2; ++mt)
                #pragma unroll
                for (int nt = 0; nt < 8; ++nt)
                    mma_f16(acc[mt][nt][0], acc[mt][nt][1], acc[mt][nt][2], acc[mt][nt][3],
                            a[mt][0], a[mt][1], a[mt][2], a[mt][3],
                            b[nt][0], b[nt][1]);
        }

        // Fetch next tile (overlaps the epilogue; published by the barrier below)
        if (ww == 0 && lane == 0)
            tile_s[grp] = atomicAdd(&g_tilectr, 1);

        // Epilogue (registers + atomics only — runs before the barrier,
        // overlapping peers' mma tail)
        int drow[2][2];
        #pragma unroll
        for (int mt = 0; mt < 2; ++mt)
            #pragma unroll
            for (int r = 0; r < 2; ++r)
                drow[mt][r] = __ldg(&g_dst[ebase + wm * 32 + mt * 16 + gg + r * 8]);

        #pragma unroll
        for (int mt = 0; mt < 2; ++mt) {
            #pragma unroll
            for (int nt = 0; nt < 8; ++nt) {
                int col = wn * 64 + nt * 8 + tg * 2;
                #pragma unroll
                for (int i = 0; i < 4; ++i) {
                    float v = acc[mt][nt][i] + ((i & 1) ? b2p[nt].y : b2p[nt].x);
                    if (v > 0.f) {
                        atomicMax(outI + drow[mt][i >> 1] * COUT + col + (i & 1),
                                  __float_as_int(v));
                    }
                }
            }
        }

        // Protect hb (mma reads) from next iteration's gather writes AND
        // publish tile_s[grp]
        asm volatile("bar.sync %0, 128;" :: "r"(barid) : "memory");
        tile = tile_s[grp];
    }
}

// ---------------------------------------------------------------------------
// Launch — exactly 4 kernels; edge_kernel is #4 (the one ncu profiles)
// ---------------------------------------------------------------------------
extern "C" void kernel_launch(void* const* d_in, const int* in_sizes, int n_in,
                              void* d_out, int out_size) {
    const float* x        = (const float*)d_in[0];
    const int*   eiw      = (const int*)d_in[1];
    const float* bn_gamma = (const float*)d_in[2];
    const float* bn_beta  = (const float*)d_in[3];
    const float* bn_mean  = (const float*)d_in[4];
    const float* bn_var   = (const float*)d_in[5];
    const float* W1       = (const float*)d_in[6];
    const float* b1       = (const float*)d_in[7];
    const float* W2       = (const float*)d_in[8];
    const float* b2       = (const float*)d_in[9];

    cudaFuncSetAttribute(edge_kernel, cudaFuncAttributeMaxDynamicSharedMemorySize, SMEM_BYTES);

    extract_fused_kernel<<<(NEDGES + 255) / 256, 256>>>(eiw, (float4*)d_out);      // 1
    dim3 g1((NNODES + 63) / 64, 512 / 64);
    gemm_fused_kernel<<<g1, 256>>>(x, bn_gamma, bn_beta, bn_mean, bn_var, W1, b1); // 2
    prep_w2t<<<128, 256>>>(W2);                                                    // 3
    edge_kernel<<<152, 512, SMEM_BYTES>>>(b2, (int*)d_out);                        // 4
}

// round 16
// speedup vs baseline: 1.1592x; 1.0217x over previous
#include <cuda_runtime.h>
#include <cuda_fp16.h>
#include <cstdint>

// Problem constants (fixed shapes)
#define NNODES 10000
#define NEDGES 640000
#define CIN    128
#define COUT   128
#define HDIM   256
#define BN_EPS 1e-5f

// ---------------------------------------------------------------------------
// Scratch (__device__ globals; no allocation allowed)
// ---------------------------------------------------------------------------
__device__ __align__(16) __half g_ABh[NNODES * 512];  // [n][0:256]=A' (dst), [n][256:512]=B (src)
__device__ __align__(16) __half g_W2h[COUT * HDIM];   // W2^T [n][k], fp16
__device__ int    g_edge[NEDGES];                     // packed: src | (dst<<16)
__device__ int    g_tilectr;                          // dynamic tile ticket

// ---------------------------------------------------------------------------
// fp16 mma m16n8k16 (fp32 accumulate) + ldmatrix helpers
// ---------------------------------------------------------------------------
__device__ __forceinline__ void mma_f16(float& c0, float& c1, float& c2, float& c3,
                                        uint32_t a0, uint32_t a1, uint32_t a2, uint32_t a3,
                                        uint32_t b0, uint32_t b1) {
    asm volatile(
        "mma.sync.aligned.m16n8k16.row.col.f32.f16.f16.f32 "
        "{%0,%1,%2,%3}, {%4,%5,%6,%7}, {%8,%9}, {%0,%1,%2,%3};\n"
        : "+f"(c0), "+f"(c1), "+f"(c2), "+f"(c3)
        : "r"(a0), "r"(a1), "r"(a2), "r"(a3), "r"(b0), "r"(b1));
}

__device__ __forceinline__ void ldsm_x4(uint32_t& r0, uint32_t& r1, uint32_t& r2, uint32_t& r3,
                                        uint32_t addr) {
    asm volatile("ldmatrix.sync.aligned.m8n8.x4.shared.b16 {%0,%1,%2,%3}, [%4];"
                 : "=r"(r0), "=r"(r1), "=r"(r2), "=r"(r3) : "r"(addr));
}

// ---------------------------------------------------------------------------
// Launch #1: fused detect + extract(packed) + zero-output + ticket reset
// ---------------------------------------------------------------------------
__global__ void extract_fused_kernel(const int* __restrict__ w, float4* __restrict__ out4) {
    const int tid = threadIdx.x;
    const int i = blockIdx.x * 256 + tid;
    int v = (i < NEDGES) ? w[2 * i + 1] : 0;
    const int is64 = !__syncthreads_or(v != 0);   // block-wide verdict, globally consistent

    if (i == 0) g_tilectr = 152 * 3;              // first 456 tiles statically assigned
    if (i < NNODES * COUT / 4) out4[i] = make_float4(0.f, 0.f, 0.f, 0.f);

    if (i >= NEDGES) return;
    int s, d;
    if (is64) {
        s = w[2 * i];
        d = w[2 * (NEDGES + i)];
    } else {
        s = w[i];
        d = w[NEDGES + i];
    }
    s = min(max(s, 0), NNODES - 1);
    d = min(max(d, 0), NNODES - 1);
    g_edge[i] = s | (d << 16);
}

// ---------------------------------------------------------------------------
// Launch #2: fused prep + node GEMM on fp16 tensor cores (unchanged)
// ---------------------------------------------------------------------------
#define XS 136

__global__ __launch_bounds__(256) void gemm_fused_kernel(
    const float* __restrict__ x,
    const float* __restrict__ gamma, const float* __restrict__ beta,
    const float* __restrict__ mean, const float* __restrict__ var,
    const float* __restrict__ W1, const float* __restrict__ b1) {
    __shared__ float s_sh[CIN], t_sh[CIN];
    __shared__ float dvp[4 * 64];
    __shared__ float dv_s[64];
    __shared__ __half xs[64 * XS];
    __shared__ __half wt[64 * XS];

    const int tid = threadIdx.x;
    const int m0 = blockIdx.x * 64, n0 = blockIdx.y * 64;

    if (tid < CIN) {
        float s = gamma[tid] * rsqrtf(var[tid] + BN_EPS);
        s_sh[tid] = s;
        t_sh[tid] = beta[tid] - mean[tid] * s;
    }
    __syncthreads();

    {
        int jj = tid & 63;
        int kg = tid >> 6;
        int j = n0 + jj;
        float dacc = 0.f;
        #pragma unroll 4
        for (int k = kg * 32; k < kg * 32 + 32; ++k) {
            float wc;
            if (j < HDIM) wc = W1[k * HDIM + j] - W1[(k + CIN) * HDIM + j];
            else          wc = W1[(k + CIN) * HDIM + (j - HDIM)];
            wt[jj * XS + k] = __float2half_rn(s_sh[k] * wc);
            dacc += t_sh[k] * wc;
        }
        dvp[kg * 64 + jj] = dacc;
    }

    {
        int row = tid >> 2, q = tid & 3;
        bool ok = (m0 + row) < NNODES;
        const float* xr = x + (m0 + row) * CIN + q * 32;
        #pragma unroll
        for (int i = 0; i < 8; ++i) {
            float4 v = ok ? *(const float4*)(xr + i * 4) : make_float4(0.f, 0.f, 0.f, 0.f);
            __half2 h0 = __floats2half2_rn(v.x, v.y);
            __half2 h1 = __floats2half2_rn(v.z, v.w);
            uint2 o;
            o.x = *(uint32_t*)&h0;
            o.y = *(uint32_t*)&h1;
            *(uint2*)&xs[row * XS + q * 32 + i * 4] = o;
        }
    }
    __syncthreads();

    if (tid < 64) {
        int j = n0 + tid;
        dv_s[tid] = dvp[tid] + dvp[64 + tid] + dvp[128 + tid] + dvp[192 + tid]
                  + ((j < HDIM) ? b1[j] : 0.f);
    }

    const int lane = tid & 31;
    const int w    = tid >> 5;
    const int wm   = w & 1;
    const int wn   = w >> 1;
    const int g    = lane >> 2;
    const int tg   = lane & 3;
    const int mat  = lane >> 3, r8 = lane & 7;

    const uint32_t xs_addr = (uint32_t)__cvta_generic_to_shared(xs);
    const uint32_t wt_addr = (uint32_t)__cvta_generic_to_shared(wt);
    uint32_t aBase[2];
    #pragma unroll
    for (int mt = 0; mt < 2; ++mt) {
        int row = wm * 32 + mt * 16 + (mat & 1) * 8 + r8;
        aBase[mt] = xs_addr + (row * XS + (mat >> 1) * 8) * 2;
    }
    const uint32_t bBase = wt_addr + ((wn * 16 + (mat >> 1) * 8 + r8) * XS + (mat & 1) * 8) * 2;

    float acc[2][2][4];
    #pragma unroll
    for (int mt = 0; mt < 2; ++mt)
        #pragma unroll
        for (int nt = 0; nt < 2; ++nt)
            #pragma unroll
            for (int i = 0; i < 4; ++i) acc[mt][nt][i] = 0.f;

    #pragma unroll
    for (int ks = 0; ks < CIN / 16; ++ks) {
        uint32_t kb = ks * 32;
        uint32_t a[2][4];
        #pragma unroll
        for (int mt = 0; mt < 2; ++mt)
            ldsm_x4(a[mt][0], a[mt][1], a[mt][2], a[mt][3], aBase[mt] + kb);
        uint32_t b[2][2];
        ldsm_x4(b[0][0], b[0][1], b[1][0], b[1][1], bBase + kb);
        #pragma unroll
        for (int mt = 0; mt < 2; ++mt)
            #pragma unroll
            for (int nt = 0; nt < 2; ++nt)
                mma_f16(acc[mt][nt][0], acc[mt][nt][1], acc[mt][nt][2], acc[mt][nt][3],
                        a[mt][0], a[mt][1], a[mt][2], a[mt][3],
                        b[nt][0], b[nt][1]);
    }
    __syncthreads();

    #pragma unroll
    for (int mt = 0; mt < 2; ++mt) {
        #pragma unroll
        for (int nt = 0; nt < 2; ++nt) {
            int lc = wn * 16 + nt * 8 + tg * 2;
            float d0 = dv_s[lc], d1 = dv_s[lc + 1];
            #pragma unroll
            for (int r = 0; r < 2; ++r) {
                int row = m0 + wm * 32 + mt * 16 + g + r * 8;
                if (row < NNODES) {
                    __half2 h = __floats2half2_rn(acc[mt][nt][2 * r] + d0,
                                                  acc[mt][nt][2 * r + 1] + d1);
                    *(uint32_t*)&g_ABh[row * 512 + n0 + lc] = *(uint32_t*)&h;
                }
            }
        }
    }
}

// ---------------------------------------------------------------------------
// Launch #3: W2 transpose to [n][k] fp16
// ---------------------------------------------------------------------------
__global__ void prep_w2t(const float* __restrict__ W2) {
    int idx = blockIdx.x * 256 + threadIdx.x;
    if (idx < COUT * HDIM) {
        int n = idx >> 8, k = idx & 255;
        g_W2h[idx] = __float2half_rn(W2[k * COUT + n]);
    }
}

// ---------------------------------------------------------------------------
// Launch #4: persistent edge kernel. 384 threads/CTA, 1 CTA/SM, THREE
// independent 4-warp groups on 96-edge tiles; warp tile 48x64 (96 acc regs,
// fits the 170-reg budget at 384 threads). LDSM traffic -15%/edge vs 32x64.
// Last tile clamps edge index; duplicated edges are idempotent under max.
// ---------------------------------------------------------------------------
#define TILE_E 96
#define KS 264                        // half stride per row; conflict-free ldsm
#define NT96 ((NEDGES + TILE_E - 1) / TILE_E)   // 6667 (last tile partial)

#define W2_HALVES (COUT * KS)         // 33792
#define H_HALVES  (TILE_E * KS)       // 25344
#define SMEM_BYTES ((W2_HALVES + 3 * H_HALVES) * 2 + COUT * 4 + 16)  // ~220.2 KB

__global__ __launch_bounds__(384, 1) void edge_kernel(const float* __restrict__ b2,
                                                      int* __restrict__ outI) {
    extern __shared__ __half smem[];
    __half* W2_s = smem;                          // [128][KS]
    __half* hbase = smem + W2_HALVES;             // 3 x [96][KS]
    float*  b2_s = (float*)(hbase + 3 * H_HALVES);// [128]
    int*    tile_s = (int*)(b2_s + COUT);         // [3] next-tile slots

    const int tid  = threadIdx.x;
    const int lane = tid & 31;
    const int w    = tid >> 5;        // 0..11
    const int grp  = w >> 2;          // group 0..2
    const int ww   = w & 3;           // warp within group
    const int wm   = ww & 1;          // row band (48 rows)
    const int wn   = ww >> 1;         // col band (64 cols)
    const int gg   = lane >> 2;
    const int tg   = lane & 3;

    // W2^T into smem once (384 threads)
    for (int idx = tid; idx < COUT * HDIM / 8; idx += 384) {
        int n = idx >> 5, kc = (idx & 31) * 8;
        *(uint4*)&W2_s[n * KS + kc] = *(const uint4*)&g_W2h[n * HDIM + kc];
    }
    if (tid < COUT) b2_s[tid] = b2[tid];
    __syncthreads();

    __half* hb = hbase + grp * H_HALVES;
    const uint32_t h_addr  = (uint32_t)__cvta_generic_to_shared(hb);
    const uint32_t w2_addr = (uint32_t)__cvta_generic_to_shared(W2_s);
    const int mat = lane >> 3, r8 = lane & 7;
    uint32_t aBase[3];
    #pragma unroll
    for (int mt = 0; mt < 3; ++mt) {
        int row = wm * 48 + mt * 16 + (mat & 1) * 8 + r8;
        aBase[mt] = h_addr + (row * KS + (mat >> 1) * 8) * 2;
    }
    uint32_t bBase[4];
    #pragma unroll
    for (int p = 0; p < 4; ++p) {
        int n = wn * 64 + p * 16 + (mat >> 1) * 8 + r8;
        bBase[p] = w2_addr + (n * KS + (mat & 1) * 8) * 2;
    }

    // b2 pairs cached in registers: cols wn*64 + nt*8 + tg*2 (+1)
    float2 b2p[8];
    #pragma unroll
    for (int nt = 0; nt < 8; ++nt)
        b2p[nt] = *(float2*)&b2_s[wn * 64 + nt * 8 + tg * 2];

    const int kc8 = lane * 8;
    const int barid = grp + 1;

    int tile = blockIdx.x * 3 + grp;   // static seed; then dynamic tickets
    while (tile < NT96) {
        const int ebase = tile * TILE_E;

        // Stage 1: gather + relu -> hb (4 warps, warp = one row per pass, 24 passes)
        const __half2 z2 = __float2half2_rn(0.f);
        #pragma unroll
        for (int pass = 0; pass < 24; ++pass) {
            int row = pass * 4 + ww;
            int p = __ldg(&g_edge[min(ebase + row, NEDGES - 1)]);
            int s = p & 0xFFFF;
            int d = p >> 16;
            uint4 ua = *(const uint4*)&g_ABh[d * 512 + kc8];
            uint4 ub = *(const uint4*)&g_ABh[s * 512 + 256 + kc8];
            uint4 o;
            __half2 h;
            h = __hmax2(__hadd2(*(__half2*)&ua.x, *(__half2*)&ub.x), z2); o.x = *(uint32_t*)&h;
            h = __hmax2(__hadd2(*(__half2*)&ua.y, *(__half2*)&ub.y), z2); o.y = *(uint32_t*)&h;
            h = __hmax2(__hadd2(*(__half2*)&ua.z, *(__half2*)&ub.z), z2); o.z = *(uint32_t*)&h;
            h = __hmax2(__hadd2(*(__half2*)&ua.w, *(__half2*)&ub.w), z2); o.w = *(uint32_t*)&h;
            *(uint4*)&hb[row * KS + kc8] = o;
        }
        asm volatile("bar.sync %0, 128;" :: "r"(barid) : "memory");

        // Stage 2: fp16 mma, warp tile 48x64, group tile [96x256] @ [256x128]
        float acc[3][8][4];
        #pragma unroll
        for (int mt = 0; mt < 3; ++mt)
            #pragma unroll
            for (int nt = 0; nt < 8; ++nt)
                #pragma unroll
                for (int i = 0; i < 4; ++i) acc[mt][nt][i] = 0.f;

        #pragma unroll 4
        for (int ks = 0; ks < HDIM / 16; ++ks) {
            uint32_t kb = ks * 32;
            uint32_t a[3][4];
            #pragma unroll
            for (int mt = 0; mt < 3; ++mt)
                ldsm_x4(a[mt][0], a[mt][1], a[mt][2], a[mt][3], aBase[mt] + kb);
            uint32_t b[8][2];
            #pragma unroll
            for (int p = 0; p < 4; ++p)
                ldsm_x4(b[2 * p][0], b[2 * p][1], b[2 * p + 1][0], b[2 * p + 1][1],
                        bBase[p] + kb);
            #pragma unroll
            for (int mt = 0; mt < 3; ++mt)
                #pragma unroll
                for (int nt = 0; nt < 8; ++nt)
                    mma_f16(acc[mt][nt][0], acc[mt][nt][1], acc[mt][nt][2], acc[mt][nt][3],
                            a[mt][0], a[mt][1], a[mt][2], a[mt][3],
                            b[nt][0], b[nt][1]);
        }

        // Fetch next tile (overlaps the epilogue; published by the barrier below)
        if (ww == 0 && lane == 0)
            tile_s[grp] = atomicAdd(&g_tilectr, 1);

        // Epilogue (registers + atomics only — runs before the barrier,
        // overlapping peers' mma tail). Clamped duplicate rows recompute the
        // same edge message -> atomicMax idempotent, no guards needed.
        int drow[3][2];
        #pragma unroll
        for (int mt = 0; mt < 3; ++mt)
            #pragma unroll
            for (int r = 0; r < 2; ++r) {
                int e = min(ebase + wm * 48 + mt * 16 + gg + r * 8, NEDGES - 1);
                drow[mt][r] = __ldg(&g_edge[e]) >> 16;
            }

        #pragma unroll
        for (int mt = 0; mt < 3; ++mt) {
            #pragma unroll
            for (int nt = 0; nt < 8; ++nt) {
                int col = wn * 64 + nt * 8 + tg * 2;
                #pragma unroll
                for (int i = 0; i < 4; ++i) {
                    float v = acc[mt][nt][i] + ((i & 1) ? b2p[nt].y : b2p[nt].x);
                    if (v > 0.f) {
                        atomicMax(outI + drow[mt][i >> 1] * COUT + col + (i & 1),
                                  __float_as_int(v));
                    }
                }
            }
        }

        // Protect hb (mma reads) from next iteration's gather writes AND
        // publish tile_s[grp]
        asm volatile("bar.sync %0, 128;" :: "r"(barid) : "memory");
        tile = tile_s[grp];
    }
}

// ---------------------------------------------------------------------------
// Launch — exactly 4 kernels; edge_kernel is #4 (the one ncu profiles)
// ---------------------------------------------------------------------------
extern "C" void kernel_launch(void* const* d_in, const int* in_sizes, int n_in,
                              void* d_out, int out_size) {
    const float* x        = (const float*)d_in[0];
    const int*   eiw      = (const int*)d_in[1];
    const float* bn_gamma = (const float*)d_in[2];
    const float* bn_beta  = (const float*)d_in[3];
    const float* bn_mean  = (const float*)d_in[4];
    const float* bn_var   = (const float*)d_in[5];
    const float* W1       = (const float*)d_in[6];
    const float* b1       = (const float*)d_in[7];
    const float* W2       = (const float*)d_in[8];
    const float* b2       = (const float*)d_in[9];

    cudaFuncSetAttribute(edge_kernel, cudaFuncAttributeMaxDynamicSharedMemorySize, SMEM_BYTES);

    extract_fused_kernel<<<(NEDGES + 255) / 256, 256>>>(eiw, (float4*)d_out);      // 1
    dim3 g1((NNODES + 63) / 64, 512 / 64);
    gemm_fused_kernel<<<g1, 256>>>(x, bn_gamma, bn_beta, bn_mean, bn_var, W1, b1); // 2
    prep_w2t<<<128, 256>>>(W2);                                                    // 3
    edge_kernel<<<152, 384, SMEM_BYTES>>>(b2, (int*)d_out);                        // 4
}